// round 2
// baseline (speedup 1.0000x reference)
#include <cuda_runtime.h>
#include <math.h>

// Problem constants (fixed by the dataset: B=8000, N=512000, D=H=128)
#define MAXB 8000
#define MAXN 512000
#define DIM 128

// Scratch (allocation-free: __device__ globals)
__device__ int   g_off[MAXB + 1];
__device__ float g_mean[MAXB * DIM];
__device__ float g_mx[MAXB * DIM];
__device__ float g_yv[MAXB * DIM];
__device__ float g_ee[MAXN];

typedef unsigned long long u64;

__device__ __forceinline__ u64 pack2(float a) {
    u64 r;
    asm("mov.b64 %0, {%1, %1};" : "=l"(r) : "f"(a));
    return r;
}
__device__ __forceinline__ void fma2(u64& acc, u64 a, u64 b) {
    asm("fma.rn.f32x2 %0, %1, %2, %0;" : "+l"(acc) : "l"(a), "l"(b));
}
union PairU { u64 u; float2 f; };

// ---------------------------------------------------------------------------
// K0: exclusive prefix sum of counts -> offsets.  Single block, 1024 threads.
// ---------------------------------------------------------------------------
__global__ void scan_kernel(const int* __restrict__ counts, int B) {
    __shared__ int s[1024];
    int tid = threadIdx.x;
    const int C = (MAXB + 1023) / 1024;  // 8 elems per thread
    int base = tid * C;
    int local[C];
    int sum = 0;
#pragma unroll
    for (int i = 0; i < C; i++) {
        int v = (base + i < B) ? counts[base + i] : 0;
        local[i] = sum;       // exclusive within chunk
        sum += v;
    }
    s[tid] = sum;
    __syncthreads();
    for (int st = 1; st < 1024; st <<= 1) {
        int v = (tid >= st) ? s[tid - st] : 0;
        __syncthreads();
        s[tid] += v;
        __syncthreads();
    }
    int prefix = (tid > 0) ? s[tid - 1] : 0;
#pragma unroll
    for (int i = 0; i < C; i++)
        if (base + i < B) g_off[base + i] = prefix + local[i];
    if (tid == 1023) g_off[B] = s[1023];
}

// ---------------------------------------------------------------------------
// K1: per-graph mean and max(|.|).  One block per graph, thread = feature dim.
// 4x unrolled for MLP.
// ---------------------------------------------------------------------------
__global__ void stats_kernel(const float* __restrict__ feats) {
    int g = blockIdx.x;
    int d = threadIdx.x;
    int s = g_off[g], e = g_off[g + 1];
    float sum = 0.f, m = 0.f;
    int n = s;
    for (; n + 3 < e; n += 4) {
        float x0 = feats[(n + 0) * DIM + d];
        float x1 = feats[(n + 1) * DIM + d];
        float x2 = feats[(n + 2) * DIM + d];
        float x3 = feats[(n + 3) * DIM + d];
        sum += x0 + x1 + x2 + x3;
        m = fmaxf(m, fmaxf(fmaxf(fabsf(x0), fabsf(x1)), fmaxf(fabsf(x2), fabsf(x3))));
    }
    for (; n < e; n++) {
        float x = feats[n * DIM + d];
        sum += x;
        m = fmaxf(m, fabsf(x));
    }
    float inv = 1.f / (float)(e - s);
    g_mean[g * DIM + d] = sum * inv;
    g_mx[g * DIM + d]   = m;
}

// ---------------------------------------------------------------------------
// K2: yv[g] = vrow[g] @ W_v + b_v, where
//     vrow[g] = (g even) ? mean[g>>1] : mx[g>>1]   (interleaved-table indexing)
// 16 graphs per block; thread = output h.
// ---------------------------------------------------------------------------
#define GPB 16
__global__ void yv_kernel(const float* __restrict__ W_v,
                          const float* __restrict__ b_v) {
    __shared__ float sv[GPB][DIM];
    int h  = threadIdx.x;
    int g0 = blockIdx.x * GPB;

    for (int idx = threadIdx.x; idx < GPB * DIM; idx += blockDim.x) {
        int gi = idx / DIM, d = idx % DIM;
        int g = g0 + gi;
        const float* src = (g & 1) ? &g_mx[(g >> 1) * DIM] : &g_mean[(g >> 1) * DIM];
        sv[gi][d] = src[d];
    }
    __syncthreads();

    float acc[GPB];
    float bb = b_v[h];
#pragma unroll
    for (int gi = 0; gi < GPB; gi++) acc[gi] = bb;

    for (int d = 0; d < DIM; d++) {
        float wv = W_v[d * DIM + h];
#pragma unroll
        for (int gi = 0; gi < GPB; gi++) acc[gi] += sv[gi][d] * wv;
    }
#pragma unroll
    for (int gi = 0; gi < GPB; gi++) g_yv[(g0 + gi) * DIM + h] = acc[gi];
}

// ---------------------------------------------------------------------------
// K3: main fused kernel (packed f32x2 SGEMM).  Per 64-node tile:
//     u = feats_tile @ W_u
//     e_n = sum_h sigmoid(u[n,h] + yv[seg[n],h]) * w_e[h]
//     ee_n = (e_n != 0) ? exp(e_n) : e_n
// 128 threads: hg = tid&15 (8 h each), mg = tid>>4 (8 nodes each).
// Accumulators are packed f32x2 pairs over adjacent h columns -> FFMA2.
// ---------------------------------------------------------------------------
#define NT 64          // nodes per block
#define DT 32          // d-tile
#define FPITCH 36      // sF row pitch in floats (144B: 16B-aligned, 4-bank skew)

__global__ __launch_bounds__(128)
void gate_kernel(const float* __restrict__ feats,
                 const float* __restrict__ W_u,
                 const float* __restrict__ w_e,
                 const int* __restrict__ seg) {
    __shared__ float sW[DT][DIM];          // 16 KB
    __shared__ float sF[NT][FPITCH];       // 9 KB
    __shared__ float sred[NT][17];         // 4.3 KB
    __shared__ float swe[DIM];

    int tid   = threadIdx.x;
    int nbase = blockIdx.x * NT;
    int hg = tid & 15;         // 16 h-groups
    int mg = tid >> 4;         // 8 node-groups
    int hb = hg * 8;
    int mb = mg * 8;

    swe[tid] = w_e[tid];

    u64 acc2[8][4];            // [node][h-pair]: packed (h=2jj, 2jj+1)
    u64 zero = pack2(0.f);
#pragma unroll
    for (int i = 0; i < 8; i++)
#pragma unroll
        for (int j = 0; j < 4; j++) acc2[i][j] = zero;

    for (int t = 0; t < DIM / DT; t++) {
        // load W_u tile [DT][128] : 1024 float4
        for (int idx = tid; idx < (DT * DIM) / 4; idx += 128) {
            int row = idx >> 5, c4 = idx & 31;
            *(float4*)&sW[row][c4 * 4] =
                *(const float4*)&W_u[(t * DT + row) * DIM + c4 * 4];
        }
        // load feats tile [NT][DT] : 512 float4
        for (int idx = tid; idx < (NT * DT) / 4; idx += 128) {
            int row = idx >> 3, c4 = idx & 7;
            *(float4*)&sF[row][c4 * 4] =
                *(const float4*)&feats[(nbase + row) * DIM + t * DT + c4 * 4];
        }
        __syncthreads();

#pragma unroll
        for (int d = 0; d < DT; d += 4) {
            // A operands: 8 nodes x 4 d-values
            float4 av[8];
#pragma unroll
            for (int i = 0; i < 8; i++)
                av[i] = *(const float4*)&sF[mb + i][d];
            // B operands: 4 d-rows x 8 h, loaded directly as packed pairs.
            // 32B-aligned (hb is a multiple of 8 floats; row = 512B).
            ulonglong2 bA[4], bB[4];
#pragma unroll
            for (int dk = 0; dk < 4; dk++) {
                bA[dk] = *(const ulonglong2*)&sW[d + dk][hb];      // pairs (0,1),(2,3)
                bB[dk] = *(const ulonglong2*)&sW[d + dk][hb + 4];  // pairs (4,5),(6,7)
            }
#pragma unroll
            for (int dk = 0; dk < 4; dk++) {
#pragma unroll
                for (int i = 0; i < 8; i++) {
                    float a = (dk == 0) ? av[i].x :
                              (dk == 1) ? av[i].y :
                              (dk == 2) ? av[i].z : av[i].w;
                    u64 a2 = pack2(a);
                    fma2(acc2[i][0], a2, bA[dk].x);
                    fma2(acc2[i][1], a2, bA[dk].y);
                    fma2(acc2[i][2], a2, bB[dk].x);
                    fma2(acc2[i][3], a2, bB[dk].y);
                }
            }
        }
        __syncthreads();
    }

    // Epilogue: add yv[seg[n]], sigmoid, dot with w_e, reduce over h-groups.
#pragma unroll
    for (int i = 0; i < 8; i++) {
        int n = nbase + mb + i;
        int g = seg[n];
        const float* yvp = &g_yv[g * DIM + hb];
        float p = 0.f;
#pragma unroll
        for (int jj = 0; jj < 4; jj++) {
            PairU pu; pu.u = acc2[i][jj];
            float v0 = pu.f.x + yvp[2 * jj];
            float v1 = pu.f.y + yvp[2 * jj + 1];
            float s0 = 1.f / (1.f + expf(-v0));
            float s1 = 1.f / (1.f + expf(-v1));
            p += s0 * swe[hb + 2 * jj] + s1 * swe[hb + 2 * jj + 1];
        }
        sred[mb + i][hg] = p;
    }
    __syncthreads();

    if (tid < NT) {
        float e = 0.f;
#pragma unroll
        for (int k = 0; k < 16; k++) e += sred[tid][k];
        int n = nbase + tid;
        g_ee[n] = (e != 0.f) ? expf(e) : e;
    }
}

// ---------------------------------------------------------------------------
// K4: attention-weighted pooling.  One block per graph, thread = dim.
// out[g, 0, d] = sum_n ee_n * feats[n,d] / sum_n ee_n      (4x unrolled)
// ---------------------------------------------------------------------------
__global__ void pool_kernel(const float* __restrict__ feats,
                            float* __restrict__ out) {
    int g = blockIdx.x;
    int d = threadIdx.x;
    int s = g_off[g], e = g_off[g + 1];
    float num = 0.f, den = 0.f;
    int n = s;
    for (; n + 3 < e; n += 4) {
        float w0 = g_ee[n + 0], w1 = g_ee[n + 1];
        float w2 = g_ee[n + 2], w3 = g_ee[n + 3];
        float x0 = feats[(n + 0) * DIM + d];
        float x1 = feats[(n + 1) * DIM + d];
        float x2 = feats[(n + 2) * DIM + d];
        float x3 = feats[(n + 3) * DIM + d];
        den += (w0 + w1) + (w2 + w3);
        num += w0 * x0 + w1 * x1 + w2 * x2 + w3 * x3;
    }
    for (; n < e; n++) {
        float w = g_ee[n];
        den += w;
        num += w * feats[n * DIM + d];
    }
    out[g * DIM + d] = num / den;
}

// ---------------------------------------------------------------------------
// Launch
// ---------------------------------------------------------------------------
extern "C" void kernel_launch(void* const* d_in, const int* in_sizes, int n_in,
                              void* d_out, int out_size) {
    const float* feats = (const float*)d_in[0];
    const float* W_u   = (const float*)d_in[1];
    const float* W_v   = (const float*)d_in[2];
    const float* b_v   = (const float*)d_in[3];
    const float* w_e   = (const float*)d_in[4];
    const int*   seg   = (const int*)d_in[5];
    const int*   cnts  = (const int*)d_in[6];
    float*       out   = (float*)d_out;

    int N = in_sizes[0] / DIM;   // 512000
    int B = in_sizes[6];         // 8000

    scan_kernel<<<1, 1024>>>(cnts, B);
    stats_kernel<<<B, DIM>>>(feats);
    yv_kernel<<<B / GPB, DIM>>>(W_v, b_v);
    gate_kernel<<<N / NT, 128>>>(feats, W_u, w_e, seg);
    pool_kernel<<<B, DIM>>>(feats, out);
}

// round 7
// speedup vs baseline: 1.0906x; 1.0906x over previous
#include <cuda_runtime.h>
#include <math.h>
#include <stdint.h>

// Problem constants (fixed by the dataset: B=8000, N=512000, D=H=128)
#define MAXB 8000
#define MAXN 512000
#define DIM 128

// Scratch (allocation-free: __device__ globals)
__device__ int   g_off[MAXB + 1];
__device__ float g_mean[MAXB * DIM];
__device__ float g_mx[MAXB * DIM];
__device__ float g_yv[MAXB * DIM];
__device__ float g_ee[MAXN];

typedef unsigned long long u64;

__device__ __forceinline__ u64 pack2(float a) {
    u64 r;
    asm("mov.b64 %0, {%1, %1};" : "=l"(r) : "f"(a));
    return r;
}
__device__ __forceinline__ void fma2(u64& acc, u64 a, u64 b) {
    asm("fma.rn.f32x2 %0, %1, %2, %0;" : "+l"(acc) : "l"(a), "l"(b));
}
union PairU { u64 u; float2 f; };

__device__ __forceinline__ uint32_t smem_u32(const void* p) {
    uint32_t a;
    asm("{ .reg .u64 t; cvta.to.shared.u64 t, %1; cvt.u32.u64 %0, t; }" : "=r"(a) : "l"(p));
    return a;
}
__device__ __forceinline__ void cp16(uint32_t dst, const void* src) {
    asm volatile("cp.async.cg.shared.global [%0], [%1], 16;" :: "r"(dst), "l"(src) : "memory");
}
__device__ __forceinline__ void cp_commit() {
    asm volatile("cp.async.commit_group;" ::: "memory");
}
template <int N>
__device__ __forceinline__ void cp_wait() {
    asm volatile("cp.async.wait_group %0;" :: "n"(N) : "memory");
}

// ---------------------------------------------------------------------------
// K0: exclusive prefix sum of counts -> offsets.  Single block, 1024 threads.
// ---------------------------------------------------------------------------
__global__ void scan_kernel(const int* __restrict__ counts, int B) {
    __shared__ int s[1024];
    int tid = threadIdx.x;
    const int C = (MAXB + 1023) / 1024;
    int base = tid * C;
    int local[C];
    int sum = 0;
#pragma unroll
    for (int i = 0; i < C; i++) {
        int v = (base + i < B) ? counts[base + i] : 0;
        local[i] = sum;
        sum += v;
    }
    s[tid] = sum;
    __syncthreads();
    for (int st = 1; st < 1024; st <<= 1) {
        int v = (tid >= st) ? s[tid - st] : 0;
        __syncthreads();
        s[tid] += v;
        __syncthreads();
    }
    int prefix = (tid > 0) ? s[tid - 1] : 0;
#pragma unroll
    for (int i = 0; i < C; i++)
        if (base + i < B) g_off[base + i] = prefix + local[i];
    if (tid == 1023) g_off[B] = s[1023];
}

// ---------------------------------------------------------------------------
// K1: per-graph mean and max(|.|).  Warp-per-row, lane = 4 cols (float4).
// ---------------------------------------------------------------------------
__global__ void stats_kernel(const float* __restrict__ feats) {
    __shared__ float ssum[4][DIM], smx[4][DIM];
    int g = blockIdx.x;
    int s = g_off[g], e = g_off[g + 1];
    int w = threadIdx.x >> 5, lane = threadIdx.x & 31;
    float4 sum = make_float4(0, 0, 0, 0), mx = make_float4(0, 0, 0, 0);
    for (int n = s + w; n < e; n += 4) {
        float4 x = *(const float4*)&feats[n * DIM + lane * 4];
        sum.x += x.x; sum.y += x.y; sum.z += x.z; sum.w += x.w;
        mx.x = fmaxf(mx.x, fabsf(x.x)); mx.y = fmaxf(mx.y, fabsf(x.y));
        mx.z = fmaxf(mx.z, fabsf(x.z)); mx.w = fmaxf(mx.w, fabsf(x.w));
    }
    *(float4*)&ssum[w][lane * 4] = sum;
    *(float4*)&smx[w][lane * 4] = mx;
    __syncthreads();
    int d = threadIdx.x;
    float t = ssum[0][d] + ssum[1][d] + ssum[2][d] + ssum[3][d];
    float m = fmaxf(fmaxf(smx[0][d], smx[1][d]), fmaxf(smx[2][d], smx[3][d]));
    g_mean[g * DIM + d] = t / (float)(e - s);
    g_mx[g * DIM + d]   = m;
}

// ---------------------------------------------------------------------------
// K2: yv[g] = vrow[g] @ W_v + b_v  (interleaved-table indexing)
// ---------------------------------------------------------------------------
#define GPB 16
__global__ void yv_kernel(const float* __restrict__ W_v,
                          const float* __restrict__ b_v) {
    __shared__ float sv[GPB][DIM];
    int h  = threadIdx.x;
    int g0 = blockIdx.x * GPB;
    for (int idx = threadIdx.x; idx < GPB * DIM; idx += blockDim.x) {
        int gi = idx / DIM, d = idx % DIM;
        int g = g0 + gi;
        const float* src = (g & 1) ? &g_mx[(g >> 1) * DIM] : &g_mean[(g >> 1) * DIM];
        sv[gi][d] = src[d];
    }
    __syncthreads();
    float acc[GPB];
    float bb = b_v[h];
#pragma unroll
    for (int gi = 0; gi < GPB; gi++) acc[gi] = bb;
    for (int d = 0; d < DIM; d++) {
        float wv = W_v[d * DIM + h];
#pragma unroll
        for (int gi = 0; gi < GPB; gi++) acc[gi] += sv[gi][d] * wv;
    }
#pragma unroll
    for (int gi = 0; gi < GPB; gi++) g_yv[(g0 + gi) * DIM + h] = acc[gi];
}

// ---------------------------------------------------------------------------
// K3: gate kernel.  FFMA2 (f32x2) register-tiled GEMM, cp.async double-buffer.
// Per 64-node tile: u = feats @ W_u; e = sigmoid(u + yv[seg]) . w_e; ee = exp.
// 128 threads: hg = tid&15 (8 h each), mg = tid>>4 (8 nodes each).
// SMEM stages: [ W-tile 32x128 (16KB) | F-tile 64x36 (9.2KB) ] x 2
// ---------------------------------------------------------------------------
#define NT 64
#define DT 32
#define FP 36                     // sF pitch in floats (144B; 16B-aligned, bank skew)
#define STG 25600                 // stage bytes: 16384 (W) + 9216 (F)
#define OFF_F 16384
#define OFF_SRED (2 * STG)                    // 51200
#define OFF_SWE  (OFF_SRED + NT * 17 * 4)     // 55552
#define GATE_SMEM (OFF_SWE + 512)             // 56064 B

__global__ __launch_bounds__(128, 4)
void gate_kernel(const float* __restrict__ feats,
                 const float* __restrict__ W_u,
                 const float* __restrict__ w_e,
                 const int* __restrict__ seg) {
    extern __shared__ char smem[];
    uint32_t sb = smem_u32(smem);

    int tid   = threadIdx.x;
    int nbase = blockIdx.x * NT;
    int hg = tid & 15;
    int mg = tid >> 4;
    int hb = hg * 8;
    int mb = mg * 8;

    float* sred = (float*)(smem + OFF_SRED);
    float* swe  = (float*)(smem + OFF_SWE);
    swe[tid] = w_e[tid];

    // issue loads for a (tile, buffer) pair: 8 W cp16 + 4 F cp16 per thread
    auto issue_tile = [&](int t, int buf) {
        uint32_t wdst = sb + buf * STG;
        uint32_t fdst = sb + buf * STG + OFF_F;
#pragma unroll
        for (int k = 0; k < 8; k++) {
            int idx = k * 128 + tid;
            int row = idx >> 5, c4 = idx & 31;
            cp16(wdst + row * 512 + c4 * 16,
                 &W_u[(t * DT + row) * DIM + c4 * 4]);
        }
#pragma unroll
        for (int k = 0; k < 4; k++) {
            int idx = k * 128 + tid;
            int row = idx >> 3, c4 = idx & 7;
            cp16(fdst + row * 144 + c4 * 16,
                 &feats[(nbase + row) * DIM + t * DT + c4 * 4]);
        }
    };

    u64 acc2[8][4];
    u64 zero = pack2(0.f);
#pragma unroll
    for (int i = 0; i < 8; i++)
#pragma unroll
        for (int j = 0; j < 4; j++) acc2[i][j] = zero;

    issue_tile(0, 0);
    cp_commit();

#pragma unroll
    for (int t = 0; t < DIM / DT; t++) {
        int buf = t & 1;
        if (t + 1 < DIM / DT) issue_tile(t + 1, (t + 1) & 1);
        cp_commit();           // one group per iteration (may be empty at t=3)
        cp_wait<1>();          // tile t's group complete
        __syncthreads();

        const float* sW = (const float*)(smem + buf * STG);
        const float* sF = (const float*)(smem + buf * STG + OFF_F);

#pragma unroll
        for (int d = 0; d < DT; d += 4) {
            float4 av[8];
#pragma unroll
            for (int i = 0; i < 8; i++)
                av[i] = *(const float4*)(sF + (mb + i) * FP + d);
#pragma unroll
            for (int dk = 0; dk < 4; dk++) {
                ulonglong2 b0 = *(const ulonglong2*)(sW + (d + dk) * DIM + hb);
                ulonglong2 b1 = *(const ulonglong2*)(sW + (d + dk) * DIM + hb + 4);
#pragma unroll
                for (int i = 0; i < 8; i++) {
                    float a = (dk == 0) ? av[i].x :
                              (dk == 1) ? av[i].y :
                              (dk == 2) ? av[i].z : av[i].w;
                    u64 a2 = pack2(a);
                    fma2(acc2[i][0], a2, b0.x);
                    fma2(acc2[i][1], a2, b0.y);
                    fma2(acc2[i][2], a2, b1.x);
                    fma2(acc2[i][3], a2, b1.y);
                }
            }
        }
        __syncthreads();   // all warps done with buf before it is refilled
    }

    // Epilogue: add yv[seg[n]], sigmoid, dot with w_e, reduce over h-groups.
#pragma unroll
    for (int i = 0; i < 8; i++) {
        int n = nbase + mb + i;
        int g = seg[n];
        const float* yvp = &g_yv[g * DIM + hb];
        float p = 0.f;
#pragma unroll
        for (int jj = 0; jj < 4; jj++) {
            PairU pu; pu.u = acc2[i][jj];
            float v0 = pu.f.x + yvp[2 * jj];
            float v1 = pu.f.y + yvp[2 * jj + 1];
            float s0 = 1.f / (1.f + __expf(-v0));
            float s1 = 1.f / (1.f + __expf(-v1));
            p += s0 * swe[hb + 2 * jj] + s1 * swe[hb + 2 * jj + 1];
        }
        sred[(mb + i) * 17 + hg] = p;
    }
    __syncthreads();

    if (tid < NT) {
        float e = 0.f;
#pragma unroll
        for (int k = 0; k < 16; k++) e += sred[tid * 17 + k];
        int n = nbase + tid;
        g_ee[n] = (e != 0.f) ? expf(e) : e;
    }
}

// ---------------------------------------------------------------------------
// K4: attention-weighted pooling.  Warp-per-row, lane = 4 cols.
// ---------------------------------------------------------------------------
__global__ void pool_kernel(const float* __restrict__ feats,
                            float* __restrict__ out) {
    __shared__ float snum[4][DIM];
    __shared__ float sden[4];
    int g = blockIdx.x;
    int s = g_off[g], e = g_off[g + 1];
    int w = threadIdx.x >> 5, lane = threadIdx.x & 31;
    float4 num = make_float4(0, 0, 0, 0);
    float den = 0.f;
    for (int n = s + w; n < e; n += 4) {
        float ww = g_ee[n];
        float4 x = *(const float4*)&feats[n * DIM + lane * 4];
        num.x += ww * x.x; num.y += ww * x.y;
        num.z += ww * x.z; num.w += ww * x.w;
        den += ww;
    }
    *(float4*)&snum[w][lane * 4] = num;
    if (lane == 0) sden[w] = den;
    __syncthreads();
    int d = threadIdx.x;
    float nt = snum[0][d] + snum[1][d] + snum[2][d] + snum[3][d];
    float dt = sden[0] + sden[1] + sden[2] + sden[3];
    out[g * DIM + d] = nt / dt;
}

// ---------------------------------------------------------------------------
// Launch
// ---------------------------------------------------------------------------
extern "C" void kernel_launch(void* const* d_in, const int* in_sizes, int n_in,
                              void* d_out, int out_size) {
    const float* feats = (const float*)d_in[0];
    const float* W_u   = (const float*)d_in[1];
    const float* W_v   = (const float*)d_in[2];
    const float* b_v   = (const float*)d_in[3];
    const float* w_e   = (const float*)d_in[4];
    const int*   seg   = (const int*)d_in[5];
    const int*   cnts  = (const int*)d_in[6];
    float*       out   = (float*)d_out;

    int N = in_sizes[0] / DIM;   // 512000
    int B = in_sizes[6];         // 8000

    cudaFuncSetAttribute(gate_kernel, cudaFuncAttributeMaxDynamicSharedMemorySize, GATE_SMEM);

    scan_kernel<<<1, 1024>>>(cnts, B);
    stats_kernel<<<B, 128>>>(feats);
    yv_kernel<<<B / GPB, DIM>>>(W_v, b_v);
    gate_kernel<<<N / NT, 128, GATE_SMEM>>>(feats, W_u, w_e, seg);
    pool_kernel<<<B, 128>>>(feats, out);
}